// round 8
// baseline (speedup 1.0000x reference)
#include <cuda_runtime.h>

#define NN 100000
#define NE 800000
#define HID 256
#define BN 32

typedef unsigned long long u64;

// Scratch (allocation-free rule: __device__ globals). 16B-aligned for float4 access.
__device__ __align__(16) float g_dinv[NN];
__device__ __align__(16) float g_hs[NN * BN];     // row-prescaled features
__device__ __align__(16) float g_agg[NN * BN];    // aggregation accumulator

// ---- f32x2 packed helpers -------------------------------------------------
__device__ __forceinline__ u64 pk2(float lo, float hi) {
    u64 r; asm("mov.b64 %0, {%1, %2};" : "=l"(r) : "f"(lo), "f"(hi)); return r;
}
__device__ __forceinline__ void upk2(float& lo, float& hi, u64 v) {
    asm("mov.b64 {%0, %1}, %2;" : "=f"(lo), "=f"(hi) : "l"(v));
}
__device__ __forceinline__ void ffma2(u64& d, u64 a, u64 b) {
    asm("fma.rn.f32x2 %0, %1, %2, %0;" : "+l"(d) : "l"(a), "l"(b));
}

// ---------------------------------------------------------------------------
// Degree / normalization
// ---------------------------------------------------------------------------
__global__ void k_init_deg() {
    int i = blockIdx.x * blockDim.x + threadIdx.x;
    if (i < NN) g_dinv[i] = 1.0f;     // self-loop contributes 1 to every degree
}

__global__ __launch_bounds__(256) void k_count_deg(const int* __restrict__ col) {
    for (int e = blockIdx.x * blockDim.x + threadIdx.x; e < NE;
         e += gridDim.x * blockDim.x)
        atomicAdd(&g_dinv[col[e]], 1.0f);
}

__global__ void k_finalize_dinv() {
    int i = blockIdx.x * blockDim.x + threadIdx.x;
    if (i < NN) g_dinv[i] = rsqrtf(g_dinv[i]);   // deg >= 1 always
}

// ---------------------------------------------------------------------------
// GEMM1: hs[n][k] = (sum_h x[n][h] * Wd[k][h]) * dinv[n]
//        agg[n][k] = hs[n][k] * dinv[n]          (self-loop init)
// 256 rows/block, 8x4 tile (f32x2), reg-prefetch pipeline over 8 H-chunks.
// Row mapping r = ry + 32*i -> stride-36 rows land banks 4 apart: conflict-free.
// ---------------------------------------------------------------------------
__global__ __launch_bounds__(256) void k_gemm_down(const float* __restrict__ x,
                                                   const float* __restrict__ Wd) {
    __shared__ __align__(16) float As[256 * 36];   // [r][hh], pad 36 (16B-aligned rows)
    __shared__ __align__(16) float Bs[32 * 36];    // [hh][k],  pad 36

    int tid = threadIdx.x;
    int cx = tid & 7;                 // 8 col-groups * 4 = 32 cols
    int ry = tid >> 3;                // 0..31; rows ry + 32*i
    int rowbase = blockIdx.x * 256;

    float4 xa[8];
    float  wb[4];

    // prefetch chunk 0 into registers
    {
#pragma unroll
        for (int q = 0; q < 8; q++) {
            int idx4 = tid + q * 256;
            int r = idx4 >> 3;
            int h4 = (idx4 & 7) << 2;
            int gr = rowbase + r; if (gr >= NN) gr = NN - 1;
            xa[q] = *(const float4*)&x[gr * HID + h4];
        }
#pragma unroll
        for (int q = 0; q < 4; q++) {
            int id = tid + q * 256;
            int k = id >> 5, hh = id & 31;
            wb[q] = Wd[k * HID + hh];
        }
    }

    u64 acc01[8], acc23[8];
#pragma unroll
    for (int i = 0; i < 8; i++) { acc01[i] = 0ULL; acc23[i] = 0ULL; }

    for (int ch = 0; ch < 8; ch++) {
        // commit staged registers to smem
#pragma unroll
        for (int q = 0; q < 8; q++) {
            int idx4 = tid + q * 256;
            int r = idx4 >> 3;
            int h4 = (idx4 & 7) << 2;
            *(float4*)&As[r * 36 + h4] = xa[q];
        }
#pragma unroll
        for (int q = 0; q < 4; q++) {
            int id = tid + q * 256;
            int k = id >> 5, hh = id & 31;
            Bs[hh * 36 + k] = wb[q];
        }
        __syncthreads();

        // prefetch next chunk (global latency hides under compute)
        if (ch + 1 < 8) {
            int hbase = (ch + 1) * 32;
#pragma unroll
            for (int q = 0; q < 8; q++) {
                int idx4 = tid + q * 256;
                int r = idx4 >> 3;
                int h4 = (idx4 & 7) << 2;
                int gr = rowbase + r; if (gr >= NN) gr = NN - 1;
                xa[q] = *(const float4*)&x[gr * HID + hbase + h4];
            }
#pragma unroll
            for (int q = 0; q < 4; q++) {
                int id = tid + q * 256;
                int k = id >> 5, hh = id & 31;
                wb[q] = Wd[k * HID + hbase + hh];
            }
        }

#pragma unroll 8
        for (int hh = 0; hh < 32; hh++) {
            u64 w01 = *(const u64*)&Bs[hh * 36 + cx * 4];
            u64 w23 = *(const u64*)&Bs[hh * 36 + cx * 4 + 2];
#pragma unroll
            for (int i = 0; i < 8; i++) {
                float a = As[(ry + 32 * i) * 36 + hh];
                u64 a2 = pk2(a, a);
                ffma2(acc01[i], a2, w01);
                ffma2(acc23[i], a2, w23);
            }
        }
        __syncthreads();
    }

#pragma unroll
    for (int i = 0; i < 8; i++) {
        int r = rowbase + ry + 32 * i;
        if (r < NN) {
            float di = g_dinv[r];
            float4 hsv;
            upk2(hsv.x, hsv.y, acc01[i]);
            upk2(hsv.z, hsv.w, acc23[i]);
            hsv.x *= di; hsv.y *= di; hsv.z *= di; hsv.w *= di;
            *(float4*)&g_hs[r * BN + cx * 4] = hsv;
            float4 ag = make_float4(hsv.x * di, hsv.y * di, hsv.z * di, hsv.w * di);
            *(float4*)&g_agg[r * BN + cx * 4] = ag;
        }
    }
}

// ---------------------------------------------------------------------------
// Edge scatter: agg[col] += hs[row] * dinv[col]
// 8 lanes/edge: one float4 gather + one red.global.add.v4.f32 per lane.
// ---------------------------------------------------------------------------
__global__ __launch_bounds__(256) void k_scatter(const int* __restrict__ rows,
                                                 const int* __restrict__ cols) {
    int t = blockIdx.x * 256 + threadIdx.x;
    int e = t >> 3;
    if (e >= NE) return;
    int j = t & 7;
    int r = rows[e];
    int c = cols[e];
    float dc = __ldg(&g_dinv[c]);
    float4 v = __ldg(((const float4*)g_hs) + (r * 8 + j));
    float4* dst = ((float4*)g_agg) + (c * 8 + j);
    asm volatile("red.global.add.v4.f32 [%0], {%1, %2, %3, %4};"
                 :: "l"(dst), "f"(v.x * dc), "f"(v.y * dc), "f"(v.z * dc), "f"(v.w * dc)
                 : "memory");
}

// ---------------------------------------------------------------------------
// ReLU + bias (float4), then pre-scale for conv2 and re-init agg w/ self-loop
// ---------------------------------------------------------------------------
__global__ __launch_bounds__(256) void k_relu_stage(const float* __restrict__ bd) {
    int i4 = blockIdx.x * blockDim.x + threadIdx.x;   // < NN*BN/4
    int n = i4 >> 3;
    float di = g_dinv[n];
    float4 a = ((const float4*)g_agg)[i4];
    float4 b = ((const float4*)bd)[i4 & 7];
    float4 v;
    v.x = fmaxf(a.x + b.x, 0.0f) * di;
    v.y = fmaxf(a.y + b.y, 0.0f) * di;
    v.z = fmaxf(a.z + b.z, 0.0f) * di;
    v.w = fmaxf(a.w + b.w, 0.0f) * di;
    ((float4*)g_hs)[i4] = v;
    float4 ag = make_float4(v.x * di, v.y * di, v.z * di, v.w * di);
    ((float4*)g_agg)[i4] = ag;
}

// ---------------------------------------------------------------------------
// GEMM2 + epilogue: out[n][h] = sum_k agg[n][k] * Wu[h][k] + bu[h] + x[n][h]
// 128 rows/block, 8 rows x 4 cols per thread; column pairs {2cx,2cx+1} and
// {128+2cx,128+2cx+1} -> conflict-free 8B-stride LDS.64 weight loads.
// Reg-prefetch of next 32-row agg tile under compute.
// ---------------------------------------------------------------------------
__global__ __launch_bounds__(256) void k_gemm_up(const float* __restrict__ x,
                                                 const float* __restrict__ Wu,
                                                 const float* __restrict__ bu,
                                                 float* __restrict__ out) {
    __shared__ __align__(16) float Bs2[32 * 260];   // [k][h] = Wu[h][k]
    __shared__ __align__(16) float As2[32 * 33];    // agg tile [r][k], pad 33

    int tid = threadIdx.x;
    int cx = tid & 63;                // 0..63 -> col pairs 2cx and 128+2cx
    int ry = tid >> 6;                // 0..3 -> rows ry*8..ry*8+7 (warp-uniform)
    int blockrow = blockIdx.x * 128;

    // stage weights once per block (coalesced reads; transposed stores)
#pragma unroll
    for (int q = 0; q < 32; q++) {
        int idx = tid + q * 256;      // 0..8191 = h*32+k
        int h = idx >> 5;
        int k = idx & 31;
        Bs2[k * 260 + h] = Wu[idx];
    }

    float2 bA = *(const float2*)&bu[2 * cx];
    float2 bB = *(const float2*)&bu[128 + 2 * cx];

    // prefetch tile 0 (32 rows x 32 k = 1024 floats, 4 per thread)
    float ap[4];
#pragma unroll
    for (int q = 0; q < 4; q++) {
        int id = tid + q * 256;
        int r = id >> 5, k = id & 31;
        int gr = blockrow + r; if (gr >= NN) gr = NN - 1;
        ap[q] = g_agg[gr * BN + k];
    }

    for (int t = 0; t < 4; t++) {
        int rb = blockrow + t * 32;
        __syncthreads();              // prev compute done / Bs2 ready
#pragma unroll
        for (int q = 0; q < 4; q++) {
            int id = tid + q * 256;
            int r = id >> 5, k = id & 31;
            As2[r * 33 + k] = ap[q];
        }
        __syncthreads();

        if (t + 1 < 4) {
            int nrb = blockrow + (t + 1) * 32;
#pragma unroll
            for (int q = 0; q < 4; q++) {
                int id = tid + q * 256;
                int r = id >> 5, k = id & 31;
                int gr = nrb + r; if (gr >= NN) gr = NN - 1;
                ap[q] = g_agg[gr * BN + k];
            }
        }

        u64 accA[8], accB[8];
#pragma unroll
        for (int i = 0; i < 8; i++) { accA[i] = 0ULL; accB[i] = 0ULL; }

#pragma unroll 8
        for (int k = 0; k < 32; k++) {
            u64 wA = *(const u64*)&Bs2[k * 260 + 2 * cx];
            u64 wB = *(const u64*)&Bs2[k * 260 + 128 + 2 * cx];
#pragma unroll
            for (int i = 0; i < 8; i++) {
                float a = As2[(ry * 8 + i) * 33 + k];
                u64 a2 = pk2(a, a);
                ffma2(accA[i], a2, wA);
                ffma2(accB[i], a2, wB);
            }
        }

#pragma unroll
        for (int i = 0; i < 8; i++) {
            int r = rb + ry * 8 + i;
            if (r < NN) {
                float2 xA = *(const float2*)&x[r * HID + 2 * cx];
                float2 xB = *(const float2*)&x[r * HID + 128 + 2 * cx];
                float2 oA, oB;
                upk2(oA.x, oA.y, accA[i]);
                upk2(oB.x, oB.y, accB[i]);
                oA.x += bA.x + xA.x;  oA.y += bA.y + xA.y;
                oB.x += bB.x + xB.x;  oB.y += bB.y + xB.y;
                *(float2*)&out[r * HID + 2 * cx] = oA;
                *(float2*)&out[r * HID + 128 + 2 * cx] = oB;
            }
        }
    }
}

// ---------------------------------------------------------------------------
extern "C" void kernel_launch(void* const* d_in, const int* in_sizes, int n_in,
                              void* d_out, int out_size) {
    // Resolve inputs by element count (robust to metadata ordering).
    // edge_index is int32 (JAX x64 disabled -> int64 request yields int32).
    const float* x = 0; const int* ei = 0;
    const float* Wd = 0; const float* bd = 0;
    const float* Wu = 0; const float* bu = 0;
    for (int i = 0; i < n_in; i++) {
        int sz = in_sizes[i];
        if (sz == NN * HID)       x  = (const float*)d_in[i];
        else if (sz == 2 * NE)    ei = (const int*)d_in[i];
        else if (sz == BN * HID) { if (!Wd) Wd = (const float*)d_in[i];
                                   else     Wu = (const float*)d_in[i]; }
        else if (sz == BN)        bd = (const float*)d_in[i];
        else if (sz == HID)       bu = (const float*)d_in[i];
    }
    float* out = (float*)d_out;

    const int* erow = ei;        // edge_index[0] = source
    const int* ecol = ei + NE;   // edge_index[1] = target

    k_init_deg<<<(NN + 255) / 256, 256>>>();
    k_count_deg<<<592, 256>>>(ecol);
    k_finalize_dinv<<<(NN + 255) / 256, 256>>>();

    k_gemm_down<<<(NN + 255) / 256, 256>>>(x, Wd);
    k_scatter<<<(NE * 8) / 256, 256>>>(erow, ecol);
    k_relu_stage<<<(NN * BN / 4 + 255) / 256, 256>>>(bd);
    k_scatter<<<(NE * 8) / 256, 256>>>(erow, ecol);
    k_gemm_up<<<(NN + 127) / 128, 256>>>(x, Wu, bu, out);
}

// round 9
// speedup vs baseline: 1.1709x; 1.1709x over previous
#include <cuda_runtime.h>
#include <cstdint>

#define NN 100000
#define NE 800000
#define HID 256
#define BN 32

typedef unsigned long long u64;

// Scratch (allocation-free rule: __device__ globals). 16B-aligned for float4 access.
__device__ __align__(16) float g_dinv[NN];
__device__ __align__(16) float g_hs[NN * BN];     // row-prescaled features
__device__ __align__(16) float g_agg[NN * BN];    // aggregation accumulator

// ---- f32x2 packed helpers -------------------------------------------------
__device__ __forceinline__ u64 pk2(float lo, float hi) {
    u64 r; asm("mov.b64 %0, {%1, %2};" : "=l"(r) : "f"(lo), "f"(hi)); return r;
}
__device__ __forceinline__ void upk2(float& lo, float& hi, u64 v) {
    asm("mov.b64 {%0, %1}, %2;" : "=f"(lo), "=f"(hi) : "l"(v));
}
__device__ __forceinline__ void ffma2(u64& d, u64 a, u64 b) {
    asm("fma.rn.f32x2 %0, %1, %2, %0;" : "+l"(d) : "l"(a), "l"(b));
}

// ---- cp.async helpers -----------------------------------------------------
__device__ __forceinline__ void cpa16(uint32_t d, const void* s) {
    asm volatile("cp.async.cg.shared.global [%0], [%1], 16;" :: "r"(d), "l"(s) : "memory");
}
__device__ __forceinline__ void cpa4(uint32_t d, const void* s) {
    asm volatile("cp.async.ca.shared.global [%0], [%1], 4;" :: "r"(d), "l"(s) : "memory");
}
#define CP_COMMIT() asm volatile("cp.async.commit_group;" ::: "memory")
#define CP_WAIT0()  asm volatile("cp.async.wait_group 0;" ::: "memory")
#define CP_WAIT1()  asm volatile("cp.async.wait_group 1;" ::: "memory")

// ---------------------------------------------------------------------------
// Degree / normalization
// ---------------------------------------------------------------------------
__global__ void k_init_deg() {
    int i = blockIdx.x * blockDim.x + threadIdx.x;
    if (i < NN) g_dinv[i] = 1.0f;     // self-loop contributes 1 to every degree
}

__global__ __launch_bounds__(256) void k_count_deg(const int* __restrict__ col) {
    for (int e = blockIdx.x * blockDim.x + threadIdx.x; e < NE;
         e += gridDim.x * blockDim.x)
        atomicAdd(&g_dinv[col[e]], 1.0f);
}

__global__ void k_finalize_dinv() {
    int i = blockIdx.x * blockDim.x + threadIdx.x;
    if (i < NN) g_dinv[i] = rsqrtf(g_dinv[i]);   // deg >= 1 always
}

// ---------------------------------------------------------------------------
// GEMM1: hs[n][k] = (sum_h x[n][h] * Wd[k][h]) * dinv[n]
//        agg[n][k] = hs[n][k] * dinv[n]          (self-loop init)
// 128 rows/block, 128 threads, 8x4 tile (f32x2), cp.async double buffer.
// Rows ry + 16*i, stride-36 rows -> banks 4 apart: conflict-free a-loads.
// ---------------------------------------------------------------------------
__global__ __launch_bounds__(128) void k_gemm_down(const float* __restrict__ x,
                                                   const float* __restrict__ Wd) {
    __shared__ __align__(16) float As[2][128 * 36];  // 36,864 B
    __shared__ __align__(16) float Bs[2][32 * 36];   //  9,216 B  (total 46,080)

    int tid = threadIdx.x;
    int cx = tid & 7;                 // 8 col-groups * 4 = 32 cols
    int ry = tid >> 3;                // 0..15; rows ry + 16*i
    int rowbase = blockIdx.x * 128;

    uint32_t as0 = (uint32_t)__cvta_generic_to_shared(&As[0][0]);
    uint32_t bs0 = (uint32_t)__cvta_generic_to_shared(&Bs[0][0]);

    // stage chunk ch into buffer buf (async)
    auto stage = [&](int ch, int buf) {
        int hbase = ch * 32;
        uint32_t asb = as0 + buf * (128 * 36 * 4);
        uint32_t bsb = bs0 + buf * (32 * 36 * 4);
#pragma unroll
        for (int q = 0; q < 8; q++) {
            int idx4 = tid + q * 128;           // 0..1023 float4 slots
            int r = idx4 >> 3;
            int h4 = (idx4 & 7) << 2;
            int gr = rowbase + r; if (gr >= NN) gr = NN - 1;
            cpa16(asb + (r * 36 + h4) * 4, &x[gr * HID + hbase + h4]);
        }
#pragma unroll
        for (int q = 0; q < 8; q++) {
            int id = tid + q * 128;             // 0..1023
            int k = id >> 5, hh = id & 31;
            cpa4(bsb + (hh * 36 + k) * 4, &Wd[k * HID + hbase + hh]);
        }
    };

    u64 acc01[8], acc23[8];
#pragma unroll
    for (int i = 0; i < 8; i++) { acc01[i] = 0ULL; acc23[i] = 0ULL; }

    stage(0, 0); CP_COMMIT();

    for (int ch = 0; ch < 8; ch++) {
        int buf = ch & 1;
        if (ch + 1 < 8) { stage(ch + 1, buf ^ 1); CP_COMMIT(); CP_WAIT1(); }
        else            { CP_WAIT0(); }
        __syncthreads();

        const float* A = &As[buf][0];
        const float* B = &Bs[buf][0];
#pragma unroll 8
        for (int hh = 0; hh < 32; hh++) {
            u64 w01 = *(const u64*)&B[hh * 36 + cx * 4];
            u64 w23 = *(const u64*)&B[hh * 36 + cx * 4 + 2];
#pragma unroll
            for (int i = 0; i < 8; i++) {
                float a = A[(ry + 16 * i) * 36 + hh];
                u64 a2 = pk2(a, a);
                ffma2(acc01[i], a2, w01);
                ffma2(acc23[i], a2, w23);
            }
        }
        __syncthreads();
    }

#pragma unroll
    for (int i = 0; i < 8; i++) {
        int r = rowbase + ry + 16 * i;
        if (r < NN) {
            float di = g_dinv[r];
            float4 hsv;
            upk2(hsv.x, hsv.y, acc01[i]);
            upk2(hsv.z, hsv.w, acc23[i]);
            hsv.x *= di; hsv.y *= di; hsv.z *= di; hsv.w *= di;
            *(float4*)&g_hs[r * BN + cx * 4] = hsv;
            float4 ag = make_float4(hsv.x * di, hsv.y * di, hsv.z * di, hsv.w * di);
            *(float4*)&g_agg[r * BN + cx * 4] = ag;
        }
    }
}

// ---------------------------------------------------------------------------
// Edge scatter: agg[col] += hs[row] * dinv[col]
// 8 lanes/edge: one float4 gather + one red.global.add.v4.f32 per lane.
// ---------------------------------------------------------------------------
__global__ __launch_bounds__(256) void k_scatter(const int* __restrict__ rows,
                                                 const int* __restrict__ cols) {
    int t = blockIdx.x * 256 + threadIdx.x;
    int e = t >> 3;
    if (e >= NE) return;
    int j = t & 7;
    int r = rows[e];
    int c = cols[e];
    float dc = __ldg(&g_dinv[c]);
    float4 v = __ldg(((const float4*)g_hs) + (r * 8 + j));
    float4* dst = ((float4*)g_agg) + (c * 8 + j);
    asm volatile("red.global.add.v4.f32 [%0], {%1, %2, %3, %4};"
                 :: "l"(dst), "f"(v.x * dc), "f"(v.y * dc), "f"(v.z * dc), "f"(v.w * dc)
                 : "memory");
}

// ---------------------------------------------------------------------------
// ReLU + bias (float4), then pre-scale for conv2 and re-init agg w/ self-loop
// ---------------------------------------------------------------------------
__global__ __launch_bounds__(256) void k_relu_stage(const float* __restrict__ bd) {
    int i4 = blockIdx.x * blockDim.x + threadIdx.x;   // < NN*BN/4
    int n = i4 >> 3;
    float di = g_dinv[n];
    float4 a = ((const float4*)g_agg)[i4];
    float4 b = ((const float4*)bd)[i4 & 7];
    float4 v;
    v.x = fmaxf(a.x + b.x, 0.0f) * di;
    v.y = fmaxf(a.y + b.y, 0.0f) * di;
    v.z = fmaxf(a.z + b.z, 0.0f) * di;
    v.w = fmaxf(a.w + b.w, 0.0f) * di;
    ((float4*)g_hs)[i4] = v;
    float4 ag = make_float4(v.x * di, v.y * di, v.z * di, v.w * di);
    ((float4*)g_agg)[i4] = ag;
}

// ---------------------------------------------------------------------------
// GEMM2 + epilogue: out[n][h] = sum_k agg[n][k] * Wu[h][k] + bu[h] + x[n][h]
// 128 rows/block, 8 rows x 4 cols per thread; column pairs {2cx,2cx+1} and
// {128+2cx,...} -> conflict-free LDS.64 weight loads. cp.async double buffer
// for agg tiles; Bs2 staged async in group 0.
// ---------------------------------------------------------------------------
__global__ __launch_bounds__(256) void k_gemm_up(const float* __restrict__ x,
                                                 const float* __restrict__ Wu,
                                                 const float* __restrict__ bu,
                                                 float* __restrict__ out) {
    __shared__ __align__(16) float Bs2[32 * 260];   // [k][h] = Wu[h][k]  (33,280 B)
    __shared__ __align__(16) float As2[2][32 * 33]; // agg tiles          ( 8,448 B)

    int tid = threadIdx.x;
    int cx = tid & 63;                // 0..63 -> col pairs 2cx and 128+2cx
    int ry = tid >> 6;                // 0..3 -> rows ry*8..ry*8+7 (warp-uniform)
    int blockrow = blockIdx.x * 128;

    uint32_t bs2b = (uint32_t)__cvta_generic_to_shared(&Bs2[0]);
    uint32_t as2b = (uint32_t)__cvta_generic_to_shared(&As2[0][0]);

    auto stage_tile = [&](int t, int buf) {
        int rb = blockrow + t * 32;
        uint32_t dst = as2b + buf * (32 * 33 * 4);
#pragma unroll
        for (int q = 0; q < 4; q++) {
            int id = tid + q * 256;   // 0..1023
            int r = id >> 5, k = id & 31;
            int gr = rb + r; if (gr >= NN) gr = NN - 1;
            cpa4(dst + (r * 33 + k) * 4, &g_agg[gr * BN + k]);
        }
    };

    // group 0: weights (transposed) + tile 0
#pragma unroll
    for (int q = 0; q < 32; q++) {
        int idx = tid + q * 256;      // 0..8191 = h*32+k
        int h = idx >> 5;
        int k = idx & 31;
        cpa4(bs2b + (k * 260 + h) * 4, &Wu[idx]);
    }
    stage_tile(0, 0);
    CP_COMMIT();

    float2 bA = *(const float2*)&bu[2 * cx];
    float2 bB = *(const float2*)&bu[128 + 2 * cx];

    for (int t = 0; t < 4; t++) {
        int buf = t & 1;
        if (t + 1 < 4) { stage_tile(t + 1, buf ^ 1); CP_COMMIT(); CP_WAIT1(); }
        else           { CP_WAIT0(); }
        __syncthreads();

        u64 accA[8], accB[8];
#pragma unroll
        for (int i = 0; i < 8; i++) { accA[i] = 0ULL; accB[i] = 0ULL; }

        const float* A = &As2[buf][0];
#pragma unroll 8
        for (int k = 0; k < 32; k++) {
            u64 wA = *(const u64*)&Bs2[k * 260 + 2 * cx];
            u64 wB = *(const u64*)&Bs2[k * 260 + 128 + 2 * cx];
#pragma unroll
            for (int i = 0; i < 8; i++) {
                float a = A[(ry * 8 + i) * 33 + k];
                u64 a2 = pk2(a, a);
                ffma2(accA[i], a2, wA);
                ffma2(accB[i], a2, wB);
            }
        }

        int rb = blockrow + t * 32;
#pragma unroll
        for (int i = 0; i < 8; i++) {
            int r = rb + ry * 8 + i;
            if (r < NN) {
                float2 xA = *(const float2*)&x[r * HID + 2 * cx];
                float2 xB = *(const float2*)&x[r * HID + 128 + 2 * cx];
                float2 oA, oB;
                upk2(oA.x, oA.y, accA[i]);
                upk2(oB.x, oB.y, accB[i]);
                oA.x += bA.x + xA.x;  oA.y += bA.y + xA.y;
                oB.x += bB.x + xB.x;  oB.y += bB.y + xB.y;
                *(float2*)&out[r * HID + 2 * cx] = oA;
                *(float2*)&out[r * HID + 128 + 2 * cx] = oB;
            }
        }
        __syncthreads();
    }
}

// ---------------------------------------------------------------------------
extern "C" void kernel_launch(void* const* d_in, const int* in_sizes, int n_in,
                              void* d_out, int out_size) {
    // Resolve inputs by element count (robust to metadata ordering).
    // edge_index is int32 (JAX x64 disabled -> int64 request yields int32).
    const float* x = 0; const int* ei = 0;
    const float* Wd = 0; const float* bd = 0;
    const float* Wu = 0; const float* bu = 0;
    for (int i = 0; i < n_in; i++) {
        int sz = in_sizes[i];
        if (sz == NN * HID)       x  = (const float*)d_in[i];
        else if (sz == 2 * NE)    ei = (const int*)d_in[i];
        else if (sz == BN * HID) { if (!Wd) Wd = (const float*)d_in[i];
                                   else     Wu = (const float*)d_in[i]; }
        else if (sz == BN)        bd = (const float*)d_in[i];
        else if (sz == HID)       bu = (const float*)d_in[i];
    }
    float* out = (float*)d_out;

    const int* erow = ei;        // edge_index[0] = source
    const int* ecol = ei + NE;   // edge_index[1] = target

    k_init_deg<<<(NN + 255) / 256, 256>>>();
    k_count_deg<<<592, 256>>>(ecol);
    k_finalize_dinv<<<(NN + 255) / 256, 256>>>();

    k_gemm_down<<<(NN + 127) / 128, 128>>>(x, Wd);
    k_scatter<<<(NE * 8) / 256, 256>>>(erow, ecol);
    k_relu_stage<<<(NN * BN / 4 + 255) / 256, 256>>>(bd);
    k_scatter<<<(NE * 8) / 256, 256>>>(erow, ecol);
    k_gemm_up<<<(NN + 127) / 128, 256>>>(x, Wu, bu, out);
}